// round 4
// baseline (speedup 1.0000x reference)
#include <cuda_runtime.h>

// Problem constants (fixed by the dataset)
#define IMG    144
#define B_     4
#define N_     1296          // tokens per batch
#define NP_    36
#define JTILES 6
#define JT     216           // N_ / JTILES  (j-tile size)
#define ROWTILES 11          // ceil(1296/128)
#define RT_ROWS 128
#define NBLOCKS (B_ * ROWTILES * JTILES)   // 264 — all co-resident (15 blocks/SM cap)

#define LOG2E 1.4426950408889634f

// Scratch: partial sums [b][jt][d(17)][N_]; per-(b,jt) maxes; barrier counters.
// Counters are monotone across graph replays (target = next multiple of 264),
// and g_bmax slots are fully rewritten each launch -> nothing needs resetting.
__device__ float    g_part[B_ * JTILES * 17 * N_];
__device__ float    g_bmax[B_ * JTILES];
__device__ unsigned g_c1;
__device__ unsigned g_c2;

// ---------------- packed f32x2 helpers ----------------
__device__ __forceinline__ unsigned long long pack2(float lo, float hi) {
    unsigned long long r;
    asm("mov.b64 %0, {%1, %2};" : "=l"(r) : "f"(lo), "f"(hi));
    return r;
}
__device__ __forceinline__ void unpack2(unsigned long long v, float& lo, float& hi) {
    asm("mov.b64 {%0, %1}, %2;" : "=f"(lo), "=f"(hi) : "l"(v));
}
#define FMA2(d, a, b, c) \
    asm("fma.rn.f32x2 %0, %1, %2, %3;" : "=l"(d) : "l"(a), "l"(b), "l"(c))
#define ADD2(d, a, b) \
    asm("add.rn.f32x2 %0, %1, %2;" : "=l"(d) : "l"(a), "l"(b))

__device__ __forceinline__ float ex2_approx(float a) {
    float r;
    asm("ex2.approx.ftz.f32 %0, %1;" : "=f"(r) : "f"(a));
    return r;
}

// Grid barrier: monotone counter, target rounds up to the next multiple of
// NBLOCKS. Launches serialize on the stream, so at launch entry the counter is
// always an exact multiple of NBLOCKS; no reset kernel needed.
__device__ __forceinline__ void grid_barrier(unsigned* c) {
    __syncthreads();
    if (threadIdx.x == 0) {
        __threadfence();
        unsigned o = atomicAdd(c, 1u);
        unsigned target = o - (o % (unsigned)NBLOCKS) + (unsigned)NBLOCKS;
        unsigned v;
        do {
            asm volatile("ld.acquire.gpu.u32 %0, [%1];" : "=r"(v) : "l"(c));
            if (v < target) __nanosleep(64);
        } while (v < target);
        __threadfence();
    }
    __syncthreads();
}

// ---------------- the single fused kernel ----------------
__global__ void __launch_bounds__(128) k_fused(const float* __restrict__ x,
                                               float* __restrict__ out) {
    __shared__ float s_tok[JT * 16];
    __shared__ float s_cj[JT];
    __shared__ float s_red[4];

    int bid = blockIdx.x;
    int jt  = bid % JTILES;
    int rt  = (bid / JTILES) % ROWTILES;
    int b   = bid / (JTILES * ROWTILES);
    int tid = threadIdx.x;
    int lane = tid & 31, warp = tid >> 5;

    const float* xb = x + b * (N_ * 16);

    // ---- fill tokens for this j-tile; fold in a running max as we go ----
    float m = 0.0f;
    {
        const float4* src = reinterpret_cast<const float4*>(xb + jt * (JT * 16));
        float4* dst = reinterpret_cast<float4*>(s_tok);
        for (int k = tid; k < JT * 4; k += 128) {
            float4 v = src[k];
            dst[k] = v;
            m = fmaxf(m, fmaxf(fmaxf(v.x, v.y), fmaxf(v.z, v.w)));
        }
    }

    // ---- phase A: rt==0 blocks publish their tile max (tiles cover x exactly)
    #pragma unroll
    for (int o = 16; o > 0; o >>= 1)
        m = fmaxf(m, __shfl_xor_sync(0xFFFFFFFFu, m, o));
    if (lane == 0) s_red[warp] = m;
    __syncthreads();
    if (rt == 0 && tid == 0) {
        float bm = fmaxf(fmaxf(s_red[0], s_red[1]), fmaxf(s_red[2], s_red[3]));
        g_bmax[b * JTILES + jt] = bm;
    }

    grid_barrier(&g_c1);

    // ---- reduce the 24 published maxes (L2 broadcasts, .cg to skip L1) ----
    float xmax = 0.0f;
    #pragma unroll
    for (int k = 0; k < B_ * JTILES; ++k)
        xmax = fmaxf(xmax, __ldcg(&g_bmax[k]));
    float s    = LOG2E / (16.0f * xmax * xmax);
    float twoS = 2.0f * s;

    // per-key constant: c_j = -q_j * s  (q_i term is softmax-row-invariant)
    for (int jj = tid; jj < JT; jj += 128) {
        const float* r = s_tok + jj * 16;
        float q = 0.f;
        #pragma unroll
        for (int d = 0; d < 16; ++d) q = fmaf(r[d], r[d], q);
        s_cj[jj] = -q * s;
    }
    __syncthreads();

    int i = rt * RT_ROWS + tid;
    if (i < N_) {
        // this thread's query token, packed into f32x2 pairs
        const float4* tiv = reinterpret_cast<const float4*>(xb + i * 16);
        float4 a0 = tiv[0], a1 = tiv[1], a2 = tiv[2], a3 = tiv[3];
        unsigned long long ti[8];
        ti[0] = pack2(a0.x, a0.y); ti[1] = pack2(a0.z, a0.w);
        ti[2] = pack2(a1.x, a1.y); ti[3] = pack2(a1.z, a1.w);
        ti[4] = pack2(a2.x, a2.y); ti[5] = pack2(a2.z, a2.w);
        ti[6] = pack2(a3.x, a3.y); ti[7] = pack2(a3.z, a3.w);

        unsigned long long acc[8];
        #pragma unroll
        for (int k = 0; k < 8; ++k) acc[k] = 0ull;
        unsigned long long accd = 0ull;   // denom duplicated in both halves

        #pragma unroll 4
        for (int jj = 0; jj < JT; ++jj) {
            const ulonglong2* rp = reinterpret_cast<const ulonglong2*>(s_tok + jj * 16);
            ulonglong2 p0 = rp[0], p1 = rp[1], p2 = rp[2], p3 = rp[3];

            unsigned long long d2a = 0ull, d2b = 0ull;   // two chains of 4
            FMA2(d2a, ti[0], p0.x, d2a);
            FMA2(d2b, ti[1], p0.y, d2b);
            FMA2(d2a, ti[2], p1.x, d2a);
            FMA2(d2b, ti[3], p1.y, d2b);
            FMA2(d2a, ti[4], p2.x, d2a);
            FMA2(d2b, ti[5], p2.y, d2b);
            FMA2(d2a, ti[6], p3.x, d2a);
            FMA2(d2b, ti[7], p3.y, d2b);
            ADD2(d2a, d2a, d2b);
            float la, ha;
            unpack2(d2a, la, ha);
            float dot = la + ha;

            float arg = fmaf(dot, twoS, s_cj[jj]);       // in [-1.45, 2.89]
            float w = ex2_approx(arg);                    // MUFU pipe (off FMA)

            unsigned long long w2 = pack2(w, w);
            FMA2(acc[0], w2, p0.x, acc[0]);
            FMA2(acc[1], w2, p0.y, acc[1]);
            FMA2(acc[2], w2, p1.x, acc[2]);
            FMA2(acc[3], w2, p1.y, acc[3]);
            FMA2(acc[4], w2, p2.x, acc[4]);
            FMA2(acc[5], w2, p2.y, acc[5]);
            FMA2(acc[6], w2, p3.x, acc[6]);
            FMA2(acc[7], w2, p3.y, acc[7]);
            unsigned long long one2 = 0x3F8000003F800000ull;  // {1.0f,1.0f}
            FMA2(accd, w2, one2, accd);
        }

        // write partials, component-major (coalesced store & coalesced read)
        float* base = g_part + (size_t)((b * JTILES + jt) * 17) * N_;
        #pragma unroll
        for (int k = 0; k < 8; ++k) {
            float lo, hi;
            unpack2(acc[k], lo, hi);
            base[(2 * k) * N_ + i]     = lo;
            base[(2 * k + 1) * N_ + i] = hi;
        }
        {
            // both halves of accd hold the SAME full denom -> use one half
            float lo, hi;
            unpack2(accd, lo, hi);
            base[16 * N_ + i] = lo;
        }
    }

    grid_barrier(&g_c2);

    // ---- final phase: blocks 0..40 combine, normalize, fold-permute ----
    int t = bid * 128 + tid;
    if (t >= B_ * N_) return;
    int fb = t / N_, fi = t - fb * N_;

    const float* p0 = g_part + (size_t)(fb * JTILES) * 17 * N_ + fi;
    float tmp[JTILES][17];
    #pragma unroll
    for (int jt2 = 0; jt2 < JTILES; ++jt2) {
        const float* base = p0 + (size_t)jt2 * 17 * N_;
        #pragma unroll
        for (int d = 0; d < 17; ++d) tmp[jt2][d] = __ldcg(&base[d * N_]);
    }

    float v[17];
    #pragma unroll
    for (int d = 0; d < 17; ++d)
        v[d] = ((tmp[0][d] + tmp[1][d]) + (tmp[2][d] + tmp[3][d]))
             + (tmp[4][d] + tmp[5][d]);

    float r = 1.0f / v[16];

    int by = fi / NP_, bx = fi - by * NP_;
    float* ob = out + fb * (IMG * IMG) + (by * 4) * IMG + bx * 4;
    #pragma unroll
    for (int ky = 0; ky < 4; ++ky) {
        float4 o;
        o.x = v[ky * 4 + 0] * r;
        o.y = v[ky * 4 + 1] * r;
        o.z = v[ky * 4 + 2] * r;
        o.w = v[ky * 4 + 3] * r;
        *reinterpret_cast<float4*>(ob + ky * IMG) = o;
    }
}

extern "C" void kernel_launch(void* const* d_in, const int* in_sizes, int n_in,
                              void* d_out, int out_size) {
    const float* x = (const float*)d_in[0];
    float* out = (float*)d_out;
    k_fused<<<NBLOCKS, 128>>>(x, out);
}